// round 3
// baseline (speedup 1.0000x reference)
#include <cuda_runtime.h>
#include <cuda_bf16.h>
#include <cstdint>

#define D       128
#define KTOT    640
#define MAXG    10048        // padded segment capacity (multiple of 64)
#define WBLK    64           // extra blocks appended for W split

// Scratch (device globals; zero-initialized at module load; rows >= G stay 0)
__device__ __align__(16) __nv_bfloat16 g_fhi[(size_t)MAXG * KTOT];
__device__ __align__(16) __nv_bfloat16 g_flo[(size_t)MAXG * KTOT];
// W stored TRANSPOSED: [n=128][k=640]
__device__ __align__(16) __nv_bfloat16 g_whi[128 * KTOT];
__device__ __align__(16) __nv_bfloat16 g_wlo[128 * KTOT];

__device__ __forceinline__ void store_split(size_t idx, float f)
{
    __nv_bfloat16 h = __float2bfloat16(f);
    g_fhi[idx] = h;
    g_flo[idx] = __float2bfloat16(f - __bfloat162float(h));
}

// ---------------------------------------------------------------------------
// Kernel 1 (fused): blocks [0,G): per-segment reduction; blocks [G,G+WBLK):
// split+transpose W. Segment offsets found by per-block binary search on the
// sorted batch ids (int64/int32 detected via words[N-1]: int64 high word = 0).
// Reduce layout: 32 threads x float4 per row, 4 row-groups, smem combine.
// feats row layout: [sum/sqrt(50) | mean | min | max | std] (5 x 128)
// ---------------------------------------------------------------------------
__global__ __launch_bounds__(128) void reduce_kernel(const float* __restrict__ x,
                                                     const int* __restrict__ words,
                                                     const float* __restrict__ W,
                                                     int N, int G)
{
    int g = blockIdx.x;
    int t = threadIdx.x;

    if (g >= G) {
        // ---- W split: 81920 elems over WBLK blocks x 128 threads ----
        int base = (g - G) * (128 * KTOT / WBLK) + t;   // 1280 per block
        #pragma unroll
        for (int i = 0; i < (128 * KTOT / WBLK) / 128; ++i) {
            int j = base + i * 128;
            int n = j / KTOT;
            int k = j - n * KTOT;
            float v = W[(size_t)k * 128 + n];
            __nv_bfloat16 h = __float2bfloat16(v);
            g_whi[j] = h;
            g_wlo[j] = __float2bfloat16(v - __bfloat162float(h));
        }
        return;
    }

    __shared__ int soff[2];
    __shared__ float s_sum[512], s_sq[512], s_mn[512], s_mx[512];

    if (t < 2) {
        int target = g + t;
        const bool is64 = (words[N - 1] == 0);
        int lo = 0, hi = N;
        while (lo < hi) {
            int mid = (lo + hi) >> 1;
            int v = is64 ? words[2 * mid] : words[mid];
            if (v < target) lo = mid + 1; else hi = mid;
        }
        soff[t] = lo;
    }
    __syncthreads();

    int s = soff[0];
    int e = soff[1];
    int cnt = e - s;

    int rg  = t >> 5;          // row-group 0..3
    int c4  = (t & 31) * 4;    // column quad

    float sm0 = 0.f, sm1 = 0.f, sm2 = 0.f, sm3 = 0.f;
    float q0 = 0.f, q1 = 0.f, q2 = 0.f, q3 = 0.f;
    float mn0 = __int_as_float(0x7f800000), mn1 = mn0, mn2 = mn0, mn3 = mn0;
    float mx0 = __int_as_float(0xff800000), mx1 = mx0, mx2 = mx0, mx3 = mx0;

    const float* base = x + (size_t)s * D + c4;
    int r = rg;
    for (; r + 4 < cnt; r += 8) {
        float4 v = *(const float4*)(base + (size_t)r * D);
        float4 w = *(const float4*)(base + (size_t)(r + 4) * D);
        sm0 += v.x; q0 = fmaf(v.x, v.x, q0); mn0 = fminf(mn0, v.x); mx0 = fmaxf(mx0, v.x);
        sm1 += v.y; q1 = fmaf(v.y, v.y, q1); mn1 = fminf(mn1, v.y); mx1 = fmaxf(mx1, v.y);
        sm2 += v.z; q2 = fmaf(v.z, v.z, q2); mn2 = fminf(mn2, v.z); mx2 = fmaxf(mx2, v.z);
        sm3 += v.w; q3 = fmaf(v.w, v.w, q3); mn3 = fminf(mn3, v.w); mx3 = fmaxf(mx3, v.w);
        sm0 += w.x; q0 = fmaf(w.x, w.x, q0); mn0 = fminf(mn0, w.x); mx0 = fmaxf(mx0, w.x);
        sm1 += w.y; q1 = fmaf(w.y, w.y, q1); mn1 = fminf(mn1, w.y); mx1 = fmaxf(mx1, w.y);
        sm2 += w.z; q2 = fmaf(w.z, w.z, q2); mn2 = fminf(mn2, w.z); mx2 = fmaxf(mx2, w.z);
        sm3 += w.w; q3 = fmaf(w.w, w.w, q3); mn3 = fminf(mn3, w.w); mx3 = fmaxf(mx3, w.w);
    }
    for (; r < cnt; r += 4) {
        float4 v = *(const float4*)(base + (size_t)r * D);
        sm0 += v.x; q0 = fmaf(v.x, v.x, q0); mn0 = fminf(mn0, v.x); mx0 = fmaxf(mx0, v.x);
        sm1 += v.y; q1 = fmaf(v.y, v.y, q1); mn1 = fminf(mn1, v.y); mx1 = fmaxf(mx1, v.y);
        sm2 += v.z; q2 = fmaf(v.z, v.z, q2); mn2 = fminf(mn2, v.z); mx2 = fmaxf(mx2, v.z);
        sm3 += v.w; q3 = fmaf(v.w, v.w, q3); mn3 = fminf(mn3, v.w); mx3 = fmaxf(mx3, v.w);
    }

    int sb = rg * 128 + c4;
    s_sum[sb] = sm0; s_sum[sb+1] = sm1; s_sum[sb+2] = sm2; s_sum[sb+3] = sm3;
    s_sq [sb] = q0;  s_sq [sb+1] = q1;  s_sq [sb+2] = q2;  s_sq [sb+3] = q3;
    s_mn [sb] = mn0; s_mn [sb+1] = mn1; s_mn [sb+2] = mn2; s_mn [sb+3] = mn3;
    s_mx [sb] = mx0; s_mx [sb+1] = mx1; s_mx [sb+2] = mx2; s_mx [sb+3] = mx3;
    __syncthreads();

    // thread t owns column t
    float sum = s_sum[t] + s_sum[t+128] + s_sum[t+256] + s_sum[t+384];
    float sq  = s_sq [t] + s_sq [t+128] + s_sq [t+256] + s_sq [t+384];
    float mn  = fminf(fminf(s_mn[t], s_mn[t+128]), fminf(s_mn[t+256], s_mn[t+384]));
    float mx  = fmaxf(fmaxf(s_mx[t], s_mx[t+128]), fmaxf(s_mx[t+256], s_mx[t+384]));

    float fc   = fmaxf((float)cnt, 1.0f);
    float mean = sum / fc;
    float stdv = sqrtf(fmaxf(sq / fc - mean * mean, 1e-9f));
    if (cnt == 0) { mn = 0.f; mx = 0.f; }

    size_t fb = (size_t)g * KTOT + t;
    store_split(fb + 0 * D, sum * 0.14142135623730951f);   // 1/sqrt(50)
    store_split(fb + 1 * D, mean);
    store_split(fb + 2 * D, mn);
    store_split(fb + 3 * D, mx);
    store_split(fb + 4 * D, stdv);
}

// ---------------------------------------------------------------------------
// Kernel 2: GEMM out[G,128] = feats[G,640] @ W + bias.
// Fused 3-combo bf16 compensation, cp.async double buffer.
// BM=64, BN=64, BK=64; 256 threads = 8 warps (2M x 4N), warp tile 32x16.
// 2 stages x 36.9KB = 73.7KB smem -> 3 blocks/SM; grid = 157*2 = 314 (1 wave).
// ---------------------------------------------------------------------------
#define SSTR    72
#define T_BUF   (64 * SSTR)                   // 4608 elems (any of Ahi/Alo/Bhi/Blo)
#define STAGE   (4 * T_BUF)                   // 18432 elems per stage
#define SMEM_ELEMS (2 * STAGE)                // 36864 elems = 73728 B

__device__ __forceinline__ void cp16(__nv_bfloat16* dst, const __nv_bfloat16* src)
{
    unsigned sa = (unsigned)__cvta_generic_to_shared(dst);
    asm volatile("cp.async.cg.shared.global [%0], [%1], 16;\n" :: "r"(sa), "l"(src));
}

#define MMA_BF16(acc, a, b0, b1)                                              \
    asm volatile(                                                             \
        "mma.sync.aligned.m16n8k16.row.col.f32.bf16.bf16.f32 "                \
        "{%0,%1,%2,%3}, {%4,%5,%6,%7}, {%8,%9}, {%0,%1,%2,%3};\n"             \
        : "+f"((acc)[0]), "+f"((acc)[1]), "+f"((acc)[2]), "+f"((acc)[3])      \
        : "r"((a)[0]), "r"((a)[1]), "r"((a)[2]), "r"((a)[3]),                 \
          "r"(b0), "r"(b1))

__global__ __launch_bounds__(256, 3) void gemm_kernel(const float* __restrict__ bias,
                                                      float* __restrict__ out, int G)
{
    extern __shared__ __nv_bfloat16 sm[];
    int tid  = threadIdx.x;
    int warp = tid >> 5;
    int lane = tid & 31;
    int wm   = warp >> 2;              // 0..1
    int wn   = warp & 3;               // 0..3
    int bm   = (blockIdx.x >> 1) * 64;
    int bn   = (blockIdx.x & 1) * 64;

    float acc[2][2][4];
    #pragma unroll
    for (int mt = 0; mt < 2; ++mt)
        #pragma unroll
        for (int nt = 0; nt < 2; ++nt)
            #pragma unroll
            for (int r2 = 0; r2 < 4; ++r2) acc[mt][nt][r2] = 0.f;

    auto load_stage = [&](int s, int kt) {
        int kb = kt * 64;
        #pragma unroll
        for (int i = 0; i < 8; ++i) {
            int c = tid + i * 256;
            int isB = c >> 10;                 // 0: A, 1: B
            int cc  = c & 1023;
            int hl  = cc >> 9;
            int c2  = cc & 511;
            int row = c2 >> 3;
            int cw  = c2 & 7;
            const __nv_bfloat16* src;
            if (isB) src = (hl ? g_wlo : g_whi) + (size_t)(bn + row) * KTOT + kb + cw * 8;
            else     src = (hl ? g_flo : g_fhi) + (size_t)(bm + row) * KTOT + kb + cw * 8;
            cp16(sm + s * STAGE + (isB * 2 + hl) * T_BUF + row * SSTR + cw * 8, src);
        }
    };

    load_stage(0, 0);
    asm volatile("cp.async.commit_group;\n");

    for (int kt = 0; kt < KTOT / 64; ++kt) {
        int s = kt & 1;
        if (kt + 1 < KTOT / 64) {
            load_stage(s ^ 1, kt + 1);
            asm volatile("cp.async.commit_group;\n");
            asm volatile("cp.async.wait_group 1;\n");
        } else {
            asm volatile("cp.async.wait_group 0;\n");
        }
        __syncthreads();

        const __nv_bfloat16* Ah = sm + s * STAGE;
        const __nv_bfloat16* Al = Ah + T_BUF;
        const __nv_bfloat16* Bh = Al + T_BUF;
        const __nv_bfloat16* Bl = Bh + T_BUF;

        #pragma unroll
        for (int ks = 0; ks < 4; ++ks) {
            int k0 = ks * 16;
            int col = k0 + (lane & 3) * 2;
            unsigned ah[2][4], al[2][4];
            #pragma unroll
            for (int mt = 0; mt < 2; ++mt) {
                int row = wm * 32 + mt * 16 + (lane >> 2);
                const __nv_bfloat16* p = Ah + row * SSTR + col;
                ah[mt][0] = *(const unsigned*)(p);
                ah[mt][1] = *(const unsigned*)(p + 8 * SSTR);
                ah[mt][2] = *(const unsigned*)(p + 8);
                ah[mt][3] = *(const unsigned*)(p + 8 * SSTR + 8);
                const __nv_bfloat16* q = Al + row * SSTR + col;
                al[mt][0] = *(const unsigned*)(q);
                al[mt][1] = *(const unsigned*)(q + 8 * SSTR);
                al[mt][2] = *(const unsigned*)(q + 8);
                al[mt][3] = *(const unsigned*)(q + 8 * SSTR + 8);
            }
            #pragma unroll
            for (int nt = 0; nt < 2; ++nt) {
                int n = wn * 16 + nt * 8 + (lane >> 2);
                const __nv_bfloat16* pb = Bh + n * SSTR + col;
                unsigned bh0 = *(const unsigned*)(pb);
                unsigned bh1 = *(const unsigned*)(pb + 8);
                const __nv_bfloat16* qb = Bl + n * SSTR + col;
                unsigned bl0 = *(const unsigned*)(qb);
                unsigned bl1 = *(const unsigned*)(qb + 8);
                #pragma unroll
                for (int mt = 0; mt < 2; ++mt) {
                    MMA_BF16(acc[mt][nt], ah[mt], bh0, bh1);
                    MMA_BF16(acc[mt][nt], ah[mt], bl0, bl1);
                    MMA_BF16(acc[mt][nt], al[mt], bh0, bh1);
                }
            }
        }
        __syncthreads();
    }

    #pragma unroll
    for (int mt = 0; mt < 2; ++mt) {
        #pragma unroll
        for (int nt = 0; nt < 2; ++nt) {
            int row = bm + wm * 32 + mt * 16 + (lane >> 2);
            int n   = bn + wn * 16 + nt * 8 + (lane & 3) * 2;
            float b0 = bias[n];
            float b1 = bias[n + 1];
            if (row < G) {
                float2 v = { acc[mt][nt][0] + b0, acc[mt][nt][1] + b1 };
                *(float2*)(out + (size_t)row * 128 + n) = v;
            }
            if (row + 8 < G) {
                float2 v = { acc[mt][nt][2] + b0, acc[mt][nt][3] + b1 };
                *(float2*)(out + (size_t)(row + 8) * 128 + n) = v;
            }
        }
    }
}

// ---------------------------------------------------------------------------
// Launch. Inputs: x[f32 N*128], batch[int64/int32 N], W[f32 640*128],
// b[f32 128], num_segments (ignored; G = out_size/128).
// ---------------------------------------------------------------------------
extern "C" void kernel_launch(void* const* d_in, const int* in_sizes, int n_in,
                              void* d_out, int out_size)
{
    const float* x     = (const float*)d_in[0];
    const int*   batch = (const int*)d_in[1];
    const float* W     = (const float*)d_in[2];
    const float* bias  = (const float*)d_in[3];
    float*       out   = (float*)d_out;

    int N = in_sizes[0] / D;
    int G = out_size / 128;

    static bool attr_done = false;
    if (!attr_done) {
        cudaFuncSetAttribute(gemm_kernel,
                             cudaFuncAttributeMaxDynamicSharedMemorySize,
                             SMEM_ELEMS * (int)sizeof(__nv_bfloat16));
        attr_done = true;
    }

    reduce_kernel<<<G + WBLK, 128>>>(x, batch, W, N, G);
    gemm_kernel<<<((G + 63) / 64) * 2, 256, SMEM_ELEMS * sizeof(__nv_bfloat16)>>>(bias, out, G);
}

// round 4
// speedup vs baseline: 1.3351x; 1.3351x over previous
#include <cuda_runtime.h>
#include <cuda_fp16.h>
#include <cstdint>

#define D       128
#define KTOT    640
#define MAXG    10048        // padded segment capacity (multiple of 64)
#define WBLK    64           // blocks for W split in prep kernel

// Scratch (device globals; zero-initialized; rows >= G stay 0 forever)
__device__ int g_segoff[MAXG + 1];
__device__ __align__(16) __half g_fh[(size_t)MAXG * KTOT];   // feats fp16
// W TRANSPOSED [n=128][k=640], fp16 hi/lo split
__device__ __align__(16) __half g_wh[128 * KTOT];
__device__ __align__(16) __half g_wl[128 * KTOT];

// ---------------------------------------------------------------------------
// Kernel 1 (prep): blocks [0,OB): segment offsets via binary search on sorted
// batch (int64/int32 detected via words[N-1]); blocks [OB,OB+WBLK): W split.
// ---------------------------------------------------------------------------
__global__ __launch_bounds__(128) void prep_kernel(const int* __restrict__ words,
                                                   const float* __restrict__ W,
                                                   int N, int G, int OB)
{
    int b = blockIdx.x;
    int t = threadIdx.x;
    if (b < OB) {
        int g = b * 128 + t;
        if (g > G) return;
        const bool is64 = (words[N - 1] == 0);
        int lo = 0, hi = N;
        while (lo < hi) {
            int mid = (lo + hi) >> 1;
            int v = is64 ? words[2 * mid] : words[mid];
            if (v < g) lo = mid + 1; else hi = mid;
        }
        g_segoff[g] = lo;
    } else {
        int base = (b - OB) * (128 * KTOT / WBLK) + t;   // 1280 per block
        #pragma unroll
        for (int i = 0; i < (128 * KTOT / WBLK) / 128; ++i) {
            int j = base + i * 128;
            int n = j / KTOT;
            int k = j - n * KTOT;
            float v = W[(size_t)k * 128 + n];
            __half h = __float2half_rn(v);
            g_wh[j] = h;
            g_wl[j] = __float2half_rn(v - __half2float(h));
        }
    }
}

// ---------------------------------------------------------------------------
// Kernel 2: per-segment reduction (streams 256MB of x). One block/segment,
// one thread per feature column, 8-way row unroll for MLP.
// feats row: [sum/sqrt(50) | mean | min | max | std] (5 x 128), fp16.
// ---------------------------------------------------------------------------
__global__ __launch_bounds__(128) void seg_reduce_kernel(const float* __restrict__ x, int G)
{
    int g = blockIdx.x;
    int d = threadIdx.x;
    int s = g_segoff[g];
    int e = g_segoff[g + 1];
    int cnt = e - s;

    float sum = 0.f, sq = 0.f;
    float mn = __int_as_float(0x7f800000);
    float mx = __int_as_float(0xff800000);

    const float* p = x + (size_t)s * D + d;
    int i = 0;
    for (; i + 8 <= cnt; i += 8) {
        float v0 = p[0];
        float v1 = p[D];
        float v2 = p[2 * D];
        float v3 = p[3 * D];
        float v4 = p[4 * D];
        float v5 = p[5 * D];
        float v6 = p[6 * D];
        float v7 = p[7 * D];
        p += 8 * D;
        sum += v0; sq = fmaf(v0, v0, sq); mn = fminf(mn, v0); mx = fmaxf(mx, v0);
        sum += v1; sq = fmaf(v1, v1, sq); mn = fminf(mn, v1); mx = fmaxf(mx, v1);
        sum += v2; sq = fmaf(v2, v2, sq); mn = fminf(mn, v2); mx = fmaxf(mx, v2);
        sum += v3; sq = fmaf(v3, v3, sq); mn = fminf(mn, v3); mx = fmaxf(mx, v3);
        sum += v4; sq = fmaf(v4, v4, sq); mn = fminf(mn, v4); mx = fmaxf(mx, v4);
        sum += v5; sq = fmaf(v5, v5, sq); mn = fminf(mn, v5); mx = fmaxf(mx, v5);
        sum += v6; sq = fmaf(v6, v6, sq); mn = fminf(mn, v6); mx = fmaxf(mx, v6);
        sum += v7; sq = fmaf(v7, v7, sq); mn = fminf(mn, v7); mx = fmaxf(mx, v7);
    }
    for (; i < cnt; ++i) {
        float v = p[0]; p += D;
        sum += v; sq = fmaf(v, v, sq); mn = fminf(mn, v); mx = fmaxf(mx, v);
    }

    float fc   = fmaxf((float)cnt, 1.0f);
    float mean = sum / fc;
    float stdv = sqrtf(fmaxf(sq / fc - mean * mean, 1e-9f));
    if (cnt == 0) { mn = 0.f; mx = 0.f; }

    size_t fb = (size_t)g * KTOT + d;
    g_fh[fb + 0 * D] = __float2half_rn(sum * 0.14142135623730951f);  // 1/sqrt(50)
    g_fh[fb + 1 * D] = __float2half_rn(mean);
    g_fh[fb + 2 * D] = __float2half_rn(mn);
    g_fh[fb + 3 * D] = __float2half_rn(mx);
    g_fh[fb + 4 * D] = __float2half_rn(stdv);
}

// ---------------------------------------------------------------------------
// Kernel 3: GEMM out[G,128] = feats[G,640] @ W + bias.
// fp16 2-pass compensation: A*Bhi + A*Blo (A single fp16; error ~3e-4 norm).
// BM=64, BN=64, BK=64; 256 threads = 8 warps (2M x 4N), warp tile 32x16.
// cp.async double buffer, 3 bufs/stage (A, Bhi, Blo), 55.3KB smem total.
// Combo-outer MMA order: same-acc MMAs spaced 4 apart.
// ---------------------------------------------------------------------------
#define SSTR    72
#define T_BUF   (64 * SSTR)                 // 4608 halfs
#define STAGE   (3 * T_BUF)                 // 13824 halfs
#define SMEM_ELEMS (2 * STAGE)              // 27648 halfs = 55296 B

__device__ __forceinline__ void cp16(__half* dst, const __half* src)
{
    unsigned sa = (unsigned)__cvta_generic_to_shared(dst);
    asm volatile("cp.async.cg.shared.global [%0], [%1], 16;\n" :: "r"(sa), "l"(src));
}

#define MMA_F16(acc, a, b0, b1)                                               \
    asm volatile(                                                             \
        "mma.sync.aligned.m16n8k16.row.col.f32.f16.f16.f32 "                  \
        "{%0,%1,%2,%3}, {%4,%5,%6,%7}, {%8,%9}, {%0,%1,%2,%3};\n"             \
        : "+f"((acc)[0]), "+f"((acc)[1]), "+f"((acc)[2]), "+f"((acc)[3])      \
        : "r"((a)[0]), "r"((a)[1]), "r"((a)[2]), "r"((a)[3]),                 \
          "r"(b0), "r"(b1))

__global__ __launch_bounds__(256, 3) void gemm_kernel(const float* __restrict__ bias,
                                                      float* __restrict__ out, int G)
{
    extern __shared__ __half sm[];
    int tid  = threadIdx.x;
    int warp = tid >> 5;
    int lane = tid & 31;
    int wm   = warp >> 2;              // 0..1
    int wn   = warp & 3;               // 0..3
    int bm   = (blockIdx.x >> 1) * 64;
    int bn   = (blockIdx.x & 1) * 64;

    float acc[2][2][4];
    #pragma unroll
    for (int mt = 0; mt < 2; ++mt)
        #pragma unroll
        for (int nt = 0; nt < 2; ++nt)
            #pragma unroll
            for (int r2 = 0; r2 < 4; ++r2) acc[mt][nt][r2] = 0.f;

    // 1536 x 16B cp.async per stage, 6 per thread
    auto load_stage = [&](int s, int kt) {
        int kb = kt * 64;
        #pragma unroll
        for (int i = 0; i < 6; ++i) {
            int c   = tid + i * 256;
            int buf = c >> 9;                  // 0:A 1:Bhi 2:Blo
            int c2  = c & 511;
            int row = c2 >> 3;
            int cw  = c2 & 7;
            const __half* src;
            if (buf == 0)      src = g_fh + (size_t)(bm + row) * KTOT + kb + cw * 8;
            else if (buf == 1) src = g_wh + (size_t)(bn + row) * KTOT + kb + cw * 8;
            else               src = g_wl + (size_t)(bn + row) * KTOT + kb + cw * 8;
            cp16(sm + s * STAGE + buf * T_BUF + row * SSTR + cw * 8, src);
        }
    };

    load_stage(0, 0);
    asm volatile("cp.async.commit_group;\n");

    for (int kt = 0; kt < KTOT / 64; ++kt) {
        int s = kt & 1;
        if (kt + 1 < KTOT / 64) {
            load_stage(s ^ 1, kt + 1);
            asm volatile("cp.async.commit_group;\n");
            asm volatile("cp.async.wait_group 1;\n");
        } else {
            asm volatile("cp.async.wait_group 0;\n");
        }
        __syncthreads();

        const __half* Ah = sm + s * STAGE;
        const __half* Bh = Ah + T_BUF;
        const __half* Bl = Bh + T_BUF;

        #pragma unroll
        for (int ks = 0; ks < 4; ++ks) {
            int k0  = ks * 16;
            int col = k0 + (lane & 3) * 2;
            unsigned a[2][4];
            #pragma unroll
            for (int mt = 0; mt < 2; ++mt) {
                int row = wm * 32 + mt * 16 + (lane >> 2);
                const __half* p = Ah + row * SSTR + col;
                a[mt][0] = *(const unsigned*)(p);
                a[mt][1] = *(const unsigned*)(p + 8 * SSTR);
                a[mt][2] = *(const unsigned*)(p + 8);
                a[mt][3] = *(const unsigned*)(p + 8 * SSTR + 8);
            }
            unsigned bh[2][2], bl[2][2];
            #pragma unroll
            for (int nt = 0; nt < 2; ++nt) {
                int n = wn * 16 + nt * 8 + (lane >> 2);
                const __half* pb = Bh + n * SSTR + col;
                bh[nt][0] = *(const unsigned*)(pb);
                bh[nt][1] = *(const unsigned*)(pb + 8);
                const __half* qb = Bl + n * SSTR + col;
                bl[nt][0] = *(const unsigned*)(qb);
                bl[nt][1] = *(const unsigned*)(qb + 8);
            }
            // combo-outer: same-acc MMAs spaced 4 issues apart
            #pragma unroll
            for (int mt = 0; mt < 2; ++mt)
                #pragma unroll
                for (int nt = 0; nt < 2; ++nt)
                    MMA_F16(acc[mt][nt], a[mt], bh[nt][0], bh[nt][1]);
            #pragma unroll
            for (int mt = 0; mt < 2; ++mt)
                #pragma unroll
                for (int nt = 0; nt < 2; ++nt)
                    MMA_F16(acc[mt][nt], a[mt], bl[nt][0], bl[nt][1]);
        }
        __syncthreads();
    }

    #pragma unroll
    for (int mt = 0; mt < 2; ++mt) {
        #pragma unroll
        for (int nt = 0; nt < 2; ++nt) {
            int row = bm + wm * 32 + mt * 16 + (lane >> 2);
            int n   = bn + wn * 16 + nt * 8 + (lane & 3) * 2;
            float b0 = bias[n];
            float b1 = bias[n + 1];
            if (row < G) {
                float2 v = { acc[mt][nt][0] + b0, acc[mt][nt][1] + b1 };
                *(float2*)(out + (size_t)row * 128 + n) = v;
            }
            if (row + 8 < G) {
                float2 v = { acc[mt][nt][2] + b0, acc[mt][nt][3] + b1 };
                *(float2*)(out + (size_t)(row + 8) * 128 + n) = v;
            }
        }
    }
}

// ---------------------------------------------------------------------------
// Launch. Inputs: x[f32 N*128], batch[int64/int32 N], W[f32 640*128],
// b[f32 128], num_segments (ignored; G = out_size/128).
// ---------------------------------------------------------------------------
extern "C" void kernel_launch(void* const* d_in, const int* in_sizes, int n_in,
                              void* d_out, int out_size)
{
    const float* x     = (const float*)d_in[0];
    const int*   batch = (const int*)d_in[1];
    const float* W     = (const float*)d_in[2];
    const float* bias  = (const float*)d_in[3];
    float*       out   = (float*)d_out;

    int N = in_sizes[0] / D;
    int G = out_size / 128;
    int OB = (G + 1 + 127) / 128;

    static bool attr_done = false;
    if (!attr_done) {
        cudaFuncSetAttribute(gemm_kernel,
                             cudaFuncAttributeMaxDynamicSharedMemorySize,
                             SMEM_ELEMS * (int)sizeof(__half));
        attr_done = true;
    }

    prep_kernel<<<OB + WBLK, 128>>>(batch, W, N, G, OB);
    seg_reduce_kernel<<<G, 128>>>(x, G);
    gemm_kernel<<<((G + 63) / 64) * 2, 256, SMEM_ELEMS * sizeof(__half)>>>(bias, out, G);
}

// round 5
// speedup vs baseline: 1.4490x; 1.0853x over previous
#include <cuda_runtime.h>
#include <cuda_fp16.h>
#include <cstdint>

#define D       128
#define KTOT    640
#define MAXG    10048        // padded segment capacity (multiple of 64)
#define WBLK    64           // blocks for W split in prep kernel

// Scratch (device globals; zero-initialized; feats rows >= G stay 0 forever)
__device__ int g_segoff[MAXG + 1];
__device__ __align__(16) __half g_fh[(size_t)MAXG * KTOT];   // feats fp16
// W TRANSPOSED [n=128][k=640], fp16 hi/lo split
__device__ __align__(16) __half g_wh[128 * KTOT];
__device__ __align__(16) __half g_wl[128 * KTOT];

// ---------------------------------------------------------------------------
// Kernel 1 (prep): blocks [0,NB): boundary scan over sorted batch ids ->
// segment offsets (streaming, coalesced). blocks [NB,NB+WBLK): W split.
// batch int64/int32 detected via words[N-1] (int64 -> high word of last = 0).
// ---------------------------------------------------------------------------
__global__ __launch_bounds__(256) void prep_kernel(const int* __restrict__ words,
                                                   const float* __restrict__ W,
                                                   int N, int G, int NB)
{
    int b = blockIdx.x;
    int t = threadIdx.x;
    if (b < NB) {
        int i = b * 256 + t;
        if (i >= N) return;
        const bool is64 = (words[N - 1] == 0);
        int bi = is64 ? words[2 * i] : words[i];
        if (i == 0) {
            for (int g = 0; g <= bi; ++g) g_segoff[g] = 0;
        }
        if (i == N - 1) {
            for (int g = bi + 1; g <= G; ++g) g_segoff[g] = N;
        } else {
            int bn = is64 ? words[2 * (i + 1)] : words[i + 1];
            for (int g = bi + 1; g <= bn; ++g) g_segoff[g] = i + 1;
        }
    } else {
        int base = (b - NB) * (128 * KTOT / WBLK) + t;   // 1280 per block
        #pragma unroll
        for (int i = 0; i < (128 * KTOT / WBLK) / 256; ++i) {
            int j = base + i * 256;
            int n = j / KTOT;
            int k = j - n * KTOT;
            float v = W[(size_t)k * 128 + n];
            __half h = __float2half_rn(v);
            g_wh[j] = h;
            g_wl[j] = __float2half_rn(v - __half2float(h));
        }
    }
}

// ---------------------------------------------------------------------------
// Kernel 2: per-segment reduction (streams 256MB of x). One block/segment.
// 128 threads = 4 warps; warp rg covers rows rg, rg+4, ... ; each lane loads
// a float4 (512B per warp-request). smem combine across the 4 row-groups.
// feats row: [sum/sqrt(50) | mean | min | max | std] (5 x 128), fp16.
// ---------------------------------------------------------------------------
__global__ __launch_bounds__(128) void seg_reduce_kernel(const float* __restrict__ x, int G)
{
    int g = blockIdx.x;
    int t = threadIdx.x;
    int rg   = t >> 5;          // row-group 0..3
    int lane = t & 31;
    int c4   = lane * 4;

    int s   = g_segoff[g];
    int e   = g_segoff[g + 1];
    int cnt = e - s;

    float sm0 = 0.f, sm1 = 0.f, sm2 = 0.f, sm3 = 0.f;
    float q0 = 0.f, q1 = 0.f, q2 = 0.f, q3 = 0.f;
    float mn0 = __int_as_float(0x7f800000), mn1 = mn0, mn2 = mn0, mn3 = mn0;
    float mx0 = __int_as_float(0xff800000), mx1 = mx0, mx2 = mx0, mx3 = mx0;

    const float* base = x + (size_t)s * D + c4;
    int r = rg;
    for (; r + 4 < cnt; r += 8) {
        float4 v = *(const float4*)(base + (size_t)r * D);
        float4 w = *(const float4*)(base + (size_t)(r + 4) * D);
        sm0 += v.x; q0 = fmaf(v.x, v.x, q0); mn0 = fminf(mn0, v.x); mx0 = fmaxf(mx0, v.x);
        sm1 += v.y; q1 = fmaf(v.y, v.y, q1); mn1 = fminf(mn1, v.y); mx1 = fmaxf(mx1, v.y);
        sm2 += v.z; q2 = fmaf(v.z, v.z, q2); mn2 = fminf(mn2, v.z); mx2 = fmaxf(mx2, v.z);
        sm3 += v.w; q3 = fmaf(v.w, v.w, q3); mn3 = fminf(mn3, v.w); mx3 = fmaxf(mx3, v.w);
        sm0 += w.x; q0 = fmaf(w.x, w.x, q0); mn0 = fminf(mn0, w.x); mx0 = fmaxf(mx0, w.x);
        sm1 += w.y; q1 = fmaf(w.y, w.y, q1); mn1 = fminf(mn1, w.y); mx1 = fmaxf(mx1, w.y);
        sm2 += w.z; q2 = fmaf(w.z, w.z, q2); mn2 = fminf(mn2, w.z); mx2 = fmaxf(mx2, w.z);
        sm3 += w.w; q3 = fmaf(w.w, w.w, q3); mn3 = fminf(mn3, w.w); mx3 = fmaxf(mx3, w.w);
    }
    for (; r < cnt; r += 4) {
        float4 v = *(const float4*)(base + (size_t)r * D);
        sm0 += v.x; q0 = fmaf(v.x, v.x, q0); mn0 = fminf(mn0, v.x); mx0 = fmaxf(mx0, v.x);
        sm1 += v.y; q1 = fmaf(v.y, v.y, q1); mn1 = fminf(mn1, v.y); mx1 = fmaxf(mx1, v.y);
        sm2 += v.z; q2 = fmaf(v.z, v.z, q2); mn2 = fminf(mn2, v.z); mx2 = fmaxf(mx2, v.z);
        sm3 += v.w; q3 = fmaf(v.w, v.w, q3); mn3 = fminf(mn3, v.w); mx3 = fmaxf(mx3, v.w);
    }

    __shared__ float s_sum[512], s_sq[512], s_mn[512], s_mx[512];
    int sb = rg * 128 + c4;
    s_sum[sb] = sm0; s_sum[sb+1] = sm1; s_sum[sb+2] = sm2; s_sum[sb+3] = sm3;
    s_sq [sb] = q0;  s_sq [sb+1] = q1;  s_sq [sb+2] = q2;  s_sq [sb+3] = q3;
    s_mn [sb] = mn0; s_mn [sb+1] = mn1; s_mn [sb+2] = mn2; s_mn [sb+3] = mn3;
    s_mx [sb] = mx0; s_mx [sb+1] = mx1; s_mx [sb+2] = mx2; s_mx [sb+3] = mx3;
    __syncthreads();

    float sum = s_sum[t] + s_sum[t+128] + s_sum[t+256] + s_sum[t+384];
    float sq  = s_sq [t] + s_sq [t+128] + s_sq [t+256] + s_sq [t+384];
    float mn  = fminf(fminf(s_mn[t], s_mn[t+128]), fminf(s_mn[t+256], s_mn[t+384]));
    float mx  = fmaxf(fmaxf(s_mx[t], s_mx[t+128]), fmaxf(s_mx[t+256], s_mx[t+384]));

    float fc   = fmaxf((float)cnt, 1.0f);
    float mean = sum / fc;
    float stdv = sqrtf(fmaxf(sq / fc - mean * mean, 1e-9f));
    if (cnt == 0) { mn = 0.f; mx = 0.f; }

    size_t fb = (size_t)g * KTOT + t;
    g_fh[fb + 0 * D] = __float2half_rn(sum * 0.14142135623730951f);  // 1/sqrt(50)
    g_fh[fb + 1 * D] = __float2half_rn(mean);
    g_fh[fb + 2 * D] = __float2half_rn(mn);
    g_fh[fb + 3 * D] = __float2half_rn(mx);
    g_fh[fb + 4 * D] = __float2half_rn(stdv);
}

// ---------------------------------------------------------------------------
// Kernel 3: GEMM out[G,128] = feats[G,640] @ W + bias.
// fp16 2-pass compensation: A*Bhi + A*Blo. BM=64, BN=64, BK=64; 256 threads,
// warp tile 32x16, cp.async double buffer (A,Bhi,Blo per stage; 55.3KB smem).
// ---------------------------------------------------------------------------
#define SSTR    72
#define T_BUF   (64 * SSTR)                 // 4608 halfs
#define STAGE   (3 * T_BUF)                 // 13824 halfs
#define SMEM_ELEMS (2 * STAGE)              // 27648 halfs = 55296 B

__device__ __forceinline__ void cp16(__half* dst, const __half* src)
{
    unsigned sa = (unsigned)__cvta_generic_to_shared(dst);
    asm volatile("cp.async.cg.shared.global [%0], [%1], 16;\n" :: "r"(sa), "l"(src));
}

#define MMA_F16(acc, a, b0, b1)                                               \
    asm volatile(                                                             \
        "mma.sync.aligned.m16n8k16.row.col.f32.f16.f16.f32 "                  \
        "{%0,%1,%2,%3}, {%4,%5,%6,%7}, {%8,%9}, {%0,%1,%2,%3};\n"             \
        : "+f"((acc)[0]), "+f"((acc)[1]), "+f"((acc)[2]), "+f"((acc)[3])      \
        : "r"((a)[0]), "r"((a)[1]), "r"((a)[2]), "r"((a)[3]),                 \
          "r"(b0), "r"(b1))

__global__ __launch_bounds__(256, 3) void gemm_kernel(const float* __restrict__ bias,
                                                      float* __restrict__ out, int G)
{
    extern __shared__ __half sm[];
    int tid  = threadIdx.x;
    int warp = tid >> 5;
    int lane = tid & 31;
    int wm   = warp >> 2;
    int wn   = warp & 3;
    int bm   = (blockIdx.x >> 1) * 64;
    int bn   = (blockIdx.x & 1) * 64;

    float acc[2][2][4];
    #pragma unroll
    for (int mt = 0; mt < 2; ++mt)
        #pragma unroll
        for (int nt = 0; nt < 2; ++nt)
            #pragma unroll
            for (int r2 = 0; r2 < 4; ++r2) acc[mt][nt][r2] = 0.f;

    auto load_stage = [&](int s, int kt) {
        int kb = kt * 64;
        #pragma unroll
        for (int i = 0; i < 6; ++i) {
            int c   = tid + i * 256;
            int buf = c >> 9;                  // 0:A 1:Bhi 2:Blo
            int c2  = c & 511;
            int row = c2 >> 3;
            int cw  = c2 & 7;
            const __half* src;
            if (buf == 0)      src = g_fh + (size_t)(bm + row) * KTOT + kb + cw * 8;
            else if (buf == 1) src = g_wh + (size_t)(bn + row) * KTOT + kb + cw * 8;
            else               src = g_wl + (size_t)(bn + row) * KTOT + kb + cw * 8;
            cp16(sm + s * STAGE + buf * T_BUF + row * SSTR + cw * 8, src);
        }
    };

    load_stage(0, 0);
    asm volatile("cp.async.commit_group;\n");

    for (int kt = 0; kt < KTOT / 64; ++kt) {
        int s = kt & 1;
        if (kt + 1 < KTOT / 64) {
            load_stage(s ^ 1, kt + 1);
            asm volatile("cp.async.commit_group;\n");
            asm volatile("cp.async.wait_group 1;\n");
        } else {
            asm volatile("cp.async.wait_group 0;\n");
        }
        __syncthreads();

        const __half* Ah = sm + s * STAGE;
        const __half* Bh = Ah + T_BUF;
        const __half* Bl = Bh + T_BUF;

        #pragma unroll
        for (int ks = 0; ks < 4; ++ks) {
            int k0  = ks * 16;
            int col = k0 + (lane & 3) * 2;
            unsigned a[2][4];
            #pragma unroll
            for (int mt = 0; mt < 2; ++mt) {
                int row = wm * 32 + mt * 16 + (lane >> 2);
                const __half* p = Ah + row * SSTR + col;
                a[mt][0] = *(const unsigned*)(p);
                a[mt][1] = *(const unsigned*)(p + 8 * SSTR);
                a[mt][2] = *(const unsigned*)(p + 8);
                a[mt][3] = *(const unsigned*)(p + 8 * SSTR + 8);
            }
            unsigned bh[2][2], bl[2][2];
            #pragma unroll
            for (int nt = 0; nt < 2; ++nt) {
                int n = wn * 16 + nt * 8 + (lane >> 2);
                const __half* pb = Bh + n * SSTR + col;
                bh[nt][0] = *(const unsigned*)(pb);
                bh[nt][1] = *(const unsigned*)(pb + 8);
                const __half* qb = Bl + n * SSTR + col;
                bl[nt][0] = *(const unsigned*)(qb);
                bl[nt][1] = *(const unsigned*)(qb + 8);
            }
            #pragma unroll
            for (int mt = 0; mt < 2; ++mt)
                #pragma unroll
                for (int nt = 0; nt < 2; ++nt)
                    MMA_F16(acc[mt][nt], a[mt], bh[nt][0], bh[nt][1]);
            #pragma unroll
            for (int mt = 0; mt < 2; ++mt)
                #pragma unroll
                for (int nt = 0; nt < 2; ++nt)
                    MMA_F16(acc[mt][nt], a[mt], bl[nt][0], bl[nt][1]);
        }
        __syncthreads();
    }

    #pragma unroll
    for (int mt = 0; mt < 2; ++mt) {
        #pragma unroll
        for (int nt = 0; nt < 2; ++nt) {
            int row = bm + wm * 32 + mt * 16 + (lane >> 2);
            int n   = bn + wn * 16 + nt * 8 + (lane & 3) * 2;
            float b0 = bias[n];
            float b1 = bias[n + 1];
            if (row < G) {
                float2 v = { acc[mt][nt][0] + b0, acc[mt][nt][1] + b1 };
                *(float2*)(out + (size_t)row * 128 + n) = v;
            }
            if (row + 8 < G) {
                float2 v = { acc[mt][nt][2] + b0, acc[mt][nt][3] + b1 };
                *(float2*)(out + (size_t)(row + 8) * 128 + n) = v;
            }
        }
    }
}

// ---------------------------------------------------------------------------
// Launch. Inputs: x[f32 N*128], batch[int64/int32 N], W[f32 640*128],
// b[f32 128], num_segments (ignored; G = out_size/128).
// ---------------------------------------------------------------------------
extern "C" void kernel_launch(void* const* d_in, const int* in_sizes, int n_in,
                              void* d_out, int out_size)
{
    const float* x     = (const float*)d_in[0];
    const int*   batch = (const int*)d_in[1];
    const float* W     = (const float*)d_in[2];
    const float* bias  = (const float*)d_in[3];
    float*       out   = (float*)d_out;

    int N = in_sizes[0] / D;
    int G = out_size / 128;
    int NB = (N + 255) / 256;

    static bool attr_done = false;
    if (!attr_done) {
        cudaFuncSetAttribute(gemm_kernel,
                             cudaFuncAttributeMaxDynamicSharedMemorySize,
                             SMEM_ELEMS * (int)sizeof(__half));
        attr_done = true;
    }

    prep_kernel<<<NB + WBLK, 256>>>(batch, W, N, G, NB);
    seg_reduce_kernel<<<G, 128>>>(x, G);
    gemm_kernel<<<((G + 63) / 64) * 2, 256, SMEM_ELEMS * sizeof(__half)>>>(bias, out, G);
}

// round 6
// speedup vs baseline: 1.5511x; 1.0705x over previous
#include <cuda_runtime.h>
#include <cuda_fp16.h>
#include <cstdint>

#define D       128
#define KTOT    640
#define MAXG    10048        // padded segment capacity (multiple of 64)

// Scratch (device globals; zero-initialized; feats rows >= G stay 0 forever)
__device__ int g_segoff[MAXG + 1];
__device__ __align__(16) __half g_fh[(size_t)MAXG * KTOT];   // feats fp16
// W TRANSPOSED [n=128][k=640], fp16 hi/lo split
__device__ __align__(16) __half g_wh[128 * KTOT];
__device__ __align__(16) __half g_wl[128 * KTOT];

// ---------------------------------------------------------------------------
// Kernel 1 (prep):
//  blocks [0,NB): boundary scan over sorted batch -> segment offsets.
//    Each thread owns 4 ids via int4 loads (int64/int32 detected once/block).
//  blocks [NB,NB+80): W split+transpose via 32x32 smem tile, both sides
//    coalesced. 20 k-tiles x 4 n-tiles.
// ---------------------------------------------------------------------------
__global__ __launch_bounds__(256) void prep_kernel(const int* __restrict__ words,
                                                   const float* __restrict__ W,
                                                   int N, int G, int NB)
{
    int b = blockIdx.x;
    int t = threadIdx.x;

    if (b < NB) {
        __shared__ int s_is64;
        if (t == 0) s_is64 = (words[N - 1] == 0);
        __syncthreads();
        const bool is64 = s_is64;

        int i0 = (b * 256 + t) * 4;
        if (i0 >= N) return;

        if (i0 + 5 <= N) {
            int v0, v1, v2, v3, v4;
            if (is64) {
                int4 w0 = *(const int4*)(words + 2 * i0);
                int4 w1 = *(const int4*)(words + 2 * i0 + 4);
                v0 = w0.x; v1 = w0.z; v2 = w1.x; v3 = w1.z;
                v4 = words[2 * (i0 + 4)];
            } else {
                int4 w0 = *(const int4*)(words + i0);
                v0 = w0.x; v1 = w0.y; v2 = w0.z; v3 = w0.w;
                v4 = words[i0 + 4];
            }
            if (i0 == 0)
                for (int g = 0; g <= v0; ++g) g_segoff[g] = 0;
            int va[5] = { v0, v1, v2, v3, v4 };
            #pragma unroll
            for (int j = 0; j < 4; ++j)
                for (int g = va[j] + 1; g <= va[j + 1]; ++g) g_segoff[g] = i0 + j + 1;
        } else {
            // scalar tail
            for (int i = i0; i < N && i < i0 + 4; ++i) {
                int bi = is64 ? words[2 * i] : words[i];
                if (i == 0)
                    for (int g = 0; g <= bi; ++g) g_segoff[g] = 0;
                if (i == N - 1) {
                    for (int g = bi + 1; g <= G; ++g) g_segoff[g] = N;
                } else {
                    int bn = is64 ? words[2 * (i + 1)] : words[i + 1];
                    for (int g = bi + 1; g <= bn; ++g) g_segoff[g] = i + 1;
                }
            }
        }
    } else {
        // ---- W split + transpose: tile tb of 20x4 grid of 32x32 tiles ----
        __shared__ float s[32][33];
        int tb = b - NB;
        int k0 = (tb % 20) * 32;
        int n0 = (tb / 20) * 32;
        int tx = t & 31;
        int ty = t >> 5;           // 0..7
        #pragma unroll
        for (int it = 0; it < 4; ++it) {
            int r = ty + it * 8;   // k offset
            s[r][tx] = W[(size_t)(k0 + r) * 128 + n0 + tx];   // coalesced read
        }
        __syncthreads();
        #pragma unroll
        for (int it = 0; it < 4; ++it) {
            int n = ty + it * 8;   // n offset
            float v = s[tx][n];
            __half h = __float2half_rn(v);
            size_t o = (size_t)(n0 + n) * KTOT + k0 + tx;     // coalesced write
            g_wh[o] = h;
            g_wl[o] = __float2half_rn(v - __half2float(h));
        }
    }
}

// ---------------------------------------------------------------------------
// Kernel 2: per-segment reduction (streams 256MB of x). One block/segment.
// 4 warps; warp rg covers rows rg, rg+4, ...; each lane loads a float4.
// feats row: [sum/sqrt(50) | mean | min | max | std] (5 x 128), fp16.
// ---------------------------------------------------------------------------
__global__ __launch_bounds__(128) void seg_reduce_kernel(const float* __restrict__ x, int G)
{
    int g = blockIdx.x;
    int t = threadIdx.x;
    int rg   = t >> 5;
    int lane = t & 31;
    int c4   = lane * 4;

    int s   = g_segoff[g];
    int e   = g_segoff[g + 1];
    int cnt = e - s;

    float sm0 = 0.f, sm1 = 0.f, sm2 = 0.f, sm3 = 0.f;
    float q0 = 0.f, q1 = 0.f, q2 = 0.f, q3 = 0.f;
    float mn0 = __int_as_float(0x7f800000), mn1 = mn0, mn2 = mn0, mn3 = mn0;
    float mx0 = __int_as_float(0xff800000), mx1 = mx0, mx2 = mx0, mx3 = mx0;

    const float* base = x + (size_t)s * D + c4;
    int r = rg;
    for (; r + 4 < cnt; r += 8) {
        float4 v = *(const float4*)(base + (size_t)r * D);
        float4 w = *(const float4*)(base + (size_t)(r + 4) * D);
        sm0 += v.x; q0 = fmaf(v.x, v.x, q0); mn0 = fminf(mn0, v.x); mx0 = fmaxf(mx0, v.x);
        sm1 += v.y; q1 = fmaf(v.y, v.y, q1); mn1 = fminf(mn1, v.y); mx1 = fmaxf(mx1, v.y);
        sm2 += v.z; q2 = fmaf(v.z, v.z, q2); mn2 = fminf(mn2, v.z); mx2 = fmaxf(mx2, v.z);
        sm3 += v.w; q3 = fmaf(v.w, v.w, q3); mn3 = fminf(mn3, v.w); mx3 = fmaxf(mx3, v.w);
        sm0 += w.x; q0 = fmaf(w.x, w.x, q0); mn0 = fminf(mn0, w.x); mx0 = fmaxf(mx0, w.x);
        sm1 += w.y; q1 = fmaf(w.y, w.y, q1); mn1 = fminf(mn1, w.y); mx1 = fmaxf(mx1, w.y);
        sm2 += w.z; q2 = fmaf(w.z, w.z, q2); mn2 = fminf(mn2, w.z); mx2 = fmaxf(mx2, w.z);
        sm3 += w.w; q3 = fmaf(w.w, w.w, q3); mn3 = fminf(mn3, w.w); mx3 = fmaxf(mx3, w.w);
    }
    for (; r < cnt; r += 4) {
        float4 v = *(const float4*)(base + (size_t)r * D);
        sm0 += v.x; q0 = fmaf(v.x, v.x, q0); mn0 = fminf(mn0, v.x); mx0 = fmaxf(mx0, v.x);
        sm1 += v.y; q1 = fmaf(v.y, v.y, q1); mn1 = fminf(mn1, v.y); mx1 = fmaxf(mx1, v.y);
        sm2 += v.z; q2 = fmaf(v.z, v.z, q2); mn2 = fminf(mn2, v.z); mx2 = fmaxf(mx2, v.z);
        sm3 += v.w; q3 = fmaf(v.w, v.w, q3); mn3 = fminf(mn3, v.w); mx3 = fmaxf(mx3, v.w);
    }

    __shared__ float s_sum[512], s_sq[512], s_mn[512], s_mx[512];
    int sb = rg * 128 + c4;
    s_sum[sb] = sm0; s_sum[sb+1] = sm1; s_sum[sb+2] = sm2; s_sum[sb+3] = sm3;
    s_sq [sb] = q0;  s_sq [sb+1] = q1;  s_sq [sb+2] = q2;  s_sq [sb+3] = q3;
    s_mn [sb] = mn0; s_mn [sb+1] = mn1; s_mn [sb+2] = mn2; s_mn [sb+3] = mn3;
    s_mx [sb] = mx0; s_mx [sb+1] = mx1; s_mx [sb+2] = mx2; s_mx [sb+3] = mx3;
    __syncthreads();

    float sum = s_sum[t] + s_sum[t+128] + s_sum[t+256] + s_sum[t+384];
    float sq  = s_sq [t] + s_sq [t+128] + s_sq [t+256] + s_sq [t+384];
    float mn  = fminf(fminf(s_mn[t], s_mn[t+128]), fminf(s_mn[t+256], s_mn[t+384]));
    float mx  = fmaxf(fmaxf(s_mx[t], s_mx[t+128]), fmaxf(s_mx[t+256], s_mx[t+384]));

    float fc   = fmaxf((float)cnt, 1.0f);
    float mean = sum / fc;
    float stdv = sqrtf(fmaxf(sq / fc - mean * mean, 1e-9f));
    if (cnt == 0) { mn = 0.f; mx = 0.f; }

    size_t fb = (size_t)g * KTOT + t;
    g_fh[fb + 0 * D] = __float2half_rn(sum * 0.14142135623730951f);  // 1/sqrt(50)
    g_fh[fb + 1 * D] = __float2half_rn(mean);
    g_fh[fb + 2 * D] = __float2half_rn(mn);
    g_fh[fb + 3 * D] = __float2half_rn(mx);
    g_fh[fb + 4 * D] = __float2half_rn(stdv);
}

// ---------------------------------------------------------------------------
// Kernel 3: GEMM out[G,128] = feats[G,640] @ W + bias.
// fp16 2-pass (A*Bhi + A*Blo). BM=64, BN=64, BK=64; 256 threads; warp 32x16.
// cp.async double buffer; fragments via ldmatrix.x4 (4 LDSM per 8 MMAs).
// ---------------------------------------------------------------------------
#define SSTR    72
#define T_BUF   (64 * SSTR)                 // 4608 halfs
#define STAGE   (3 * T_BUF)                 // 13824 halfs
#define SMEM_ELEMS (2 * STAGE)              // 55296 B

__device__ __forceinline__ void cp16(__half* dst, const __half* src)
{
    unsigned sa = (unsigned)__cvta_generic_to_shared(dst);
    asm volatile("cp.async.cg.shared.global [%0], [%1], 16;\n" :: "r"(sa), "l"(src));
}

#define LDSM4(r0, r1, r2, r3, addr)                                           \
    asm volatile("ldmatrix.sync.aligned.m8n8.x4.shared.b16 {%0,%1,%2,%3}, [%4];" \
        : "=r"(r0), "=r"(r1), "=r"(r2), "=r"(r3) : "r"(addr))

#define MMA_F16(acc, a0, a1, a2, a3, b0, b1)                                  \
    asm volatile(                                                             \
        "mma.sync.aligned.m16n8k16.row.col.f32.f16.f16.f32 "                  \
        "{%0,%1,%2,%3}, {%4,%5,%6,%7}, {%8,%9}, {%0,%1,%2,%3};\n"             \
        : "+f"((acc)[0]), "+f"((acc)[1]), "+f"((acc)[2]), "+f"((acc)[3])      \
        : "r"(a0), "r"(a1), "r"(a2), "r"(a3), "r"(b0), "r"(b1))

__global__ __launch_bounds__(256, 3) void gemm_kernel(const float* __restrict__ bias,
                                                      float* __restrict__ out, int G)
{
    extern __shared__ __half sm[];
    int tid  = threadIdx.x;
    int warp = tid >> 5;
    int lane = tid & 31;
    int wm   = warp >> 2;
    int wn   = warp & 3;
    int bm   = (blockIdx.x >> 1) * 64;
    int bn   = (blockIdx.x & 1) * 64;

    float acc[2][2][4];
    #pragma unroll
    for (int mt = 0; mt < 2; ++mt)
        #pragma unroll
        for (int nt = 0; nt < 2; ++nt)
            #pragma unroll
            for (int r2 = 0; r2 < 4; ++r2) acc[mt][nt][r2] = 0.f;

    // ldmatrix per-lane byte offsets (within a stage)
    unsigned smbase = (unsigned)__cvta_generic_to_shared(sm);
    int mat = lane >> 3, rr = lane & 7;
    // A: mats [m0-7,k0][m8-15,k0][m0-7,k8][m8-15,k8]
    unsigned offA0 = ((wm * 32 +      (mat & 1) * 8 + rr) * SSTR + (mat >> 1) * 8) * 2;
    unsigned offA1 = ((wm * 32 + 16 + (mat & 1) * 8 + rr) * SSTR + (mat >> 1) * 8) * 2;
    // B: mats [n0-7,k0][n0-7,k8][n8-15,k0][n8-15,k8]
    unsigned offB  = ((unsigned)T_BUF + (wn * 16 + (mat >> 1) * 8 + rr) * SSTR
                      + (mat & 1) * 8) * 2;

    auto load_stage = [&](int s, int kt) {
        int kb = kt * 64;
        #pragma unroll
        for (int i = 0; i < 6; ++i) {
            int c   = tid + i * 256;
            int buf = c >> 9;                  // 0:A 1:Bhi 2:Blo
            int c2  = c & 511;
            int row = c2 >> 3;
            int cw  = c2 & 7;
            const __half* src;
            if (buf == 0)      src = g_fh + (size_t)(bm + row) * KTOT + kb + cw * 8;
            else if (buf == 1) src = g_wh + (size_t)(bn + row) * KTOT + kb + cw * 8;
            else               src = g_wl + (size_t)(bn + row) * KTOT + kb + cw * 8;
            cp16(sm + s * STAGE + buf * T_BUF + row * SSTR + cw * 8, src);
        }
    };

    load_stage(0, 0);
    asm volatile("cp.async.commit_group;\n");

    for (int kt = 0; kt < KTOT / 64; ++kt) {
        int s = kt & 1;
        if (kt + 1 < KTOT / 64) {
            load_stage(s ^ 1, kt + 1);
            asm volatile("cp.async.commit_group;\n");
            asm volatile("cp.async.wait_group 1;\n");
        } else {
            asm volatile("cp.async.wait_group 0;\n");
        }
        __syncthreads();

        unsigned sOff = smbase + (unsigned)(s * STAGE) * 2;

        #pragma unroll
        for (int ks = 0; ks < 4; ++ks) {
            unsigned kOff = (unsigned)(ks * 16) * 2;
            unsigned a0[4], a1[4], bh[4], bl[4];
            LDSM4(a0[0], a0[1], a0[2], a0[3], sOff + offA0 + kOff);
            LDSM4(a1[0], a1[1], a1[2], a1[3], sOff + offA1 + kOff);
            LDSM4(bh[0], bh[1], bh[2], bh[3], sOff + offB + kOff);
            LDSM4(bl[0], bl[1], bl[2], bl[3], sOff + offB + (unsigned)(T_BUF * 2) + kOff);

            MMA_F16(acc[0][0], a0[0], a0[1], a0[2], a0[3], bh[0], bh[1]);
            MMA_F16(acc[0][1], a0[0], a0[1], a0[2], a0[3], bh[2], bh[3]);
            MMA_F16(acc[1][0], a1[0], a1[1], a1[2], a1[3], bh[0], bh[1]);
            MMA_F16(acc[1][1], a1[0], a1[1], a1[2], a1[3], bh[2], bh[3]);
            MMA_F16(acc[0][0], a0[0], a0[1], a0[2], a0[3], bl[0], bl[1]);
            MMA_F16(acc[0][1], a0[0], a0[1], a0[2], a0[3], bl[2], bl[3]);
            MMA_F16(acc[1][0], a1[0], a1[1], a1[2], a1[3], bl[0], bl[1]);
            MMA_F16(acc[1][1], a1[0], a1[1], a1[2], a1[3], bl[2], bl[3]);
        }
        __syncthreads();
    }

    #pragma unroll
    for (int mt = 0; mt < 2; ++mt) {
        #pragma unroll
        for (int nt = 0; nt < 2; ++nt) {
            int row = bm + wm * 32 + mt * 16 + (lane >> 2);
            int n   = bn + wn * 16 + nt * 8 + (lane & 3) * 2;
            float b0 = bias[n];
            float b1 = bias[n + 1];
            if (row < G) {
                float2 v = { acc[mt][nt][0] + b0, acc[mt][nt][1] + b1 };
                *(float2*)(out + (size_t)row * 128 + n) = v;
            }
            if (row + 8 < G) {
                float2 v = { acc[mt][nt][2] + b0, acc[mt][nt][3] + b1 };
                *(float2*)(out + (size_t)(row + 8) * 128 + n) = v;
            }
        }
    }
}

// ---------------------------------------------------------------------------
// Launch. Inputs: x[f32 N*128], batch[int64/int32 N], W[f32 640*128],
// b[f32 128], num_segments (ignored; G = out_size/128).
// ---------------------------------------------------------------------------
extern "C" void kernel_launch(void* const* d_in, const int* in_sizes, int n_in,
                              void* d_out, int out_size)
{
    const float* x     = (const float*)d_in[0];
    const int*   batch = (const int*)d_in[1];
    const float* W     = (const float*)d_in[2];
    const float* bias  = (const float*)d_in[3];
    float*       out   = (float*)d_out;

    int N = in_sizes[0] / D;
    int G = out_size / 128;
    int NB = (N + 1023) / 1024;

    static bool attr_done = false;
    if (!attr_done) {
        cudaFuncSetAttribute(gemm_kernel,
                             cudaFuncAttributeMaxDynamicSharedMemorySize,
                             SMEM_ELEMS * (int)sizeof(__half));
        attr_done = true;
    }

    prep_kernel<<<NB + 80, 256>>>(batch, W, N, G, NB);
    seg_reduce_kernel<<<G, 128>>>(x, G);
    gemm_kernel<<<((G + 63) / 64) * 2, 256, SMEM_ELEMS * sizeof(__half)>>>(bias, out, G);
}

// round 7
// speedup vs baseline: 1.5518x; 1.0005x over previous
#include <cuda_runtime.h>
#include <cuda_fp16.h>
#include <cstdint>

#define D       128
#define KTOT    640
#define MAXG    10048        // padded segment capacity (multiple of 64)
#define WTILES  80           // 20 k-tiles x 4 n-tiles of 32x32 for W split

// Scratch (device globals; zero-initialized; feats rows >= G stay 0 forever)
__device__ int g_segoff[MAXG + 1];
__device__ __align__(16) __half g_fh[(size_t)MAXG * KTOT];   // feats fp16
// W TRANSPOSED [n=128][k=640], fp16 hi/lo split
__device__ __align__(16) __half g_wh[128 * KTOT];
__device__ __align__(16) __half g_wl[128 * KTOT];

// ---------------------------------------------------------------------------
// Kernel 1 (scan): boundary scan over sorted batch -> segment offsets.
// Each thread owns 4 ids via int4 loads; int64/int32 detected once per block
// (int64 -> high word of last element is 0).
// ---------------------------------------------------------------------------
__global__ __launch_bounds__(256) void scan_kernel(const int* __restrict__ words,
                                                   int N, int G)
{
    __shared__ int s_is64;
    int t = threadIdx.x;
    if (t == 0) s_is64 = (words[N - 1] == 0);
    __syncthreads();
    const bool is64 = s_is64;

    int i0 = (blockIdx.x * 256 + t) * 4;
    if (i0 >= N) return;

    if (i0 + 5 <= N) {
        int v0, v1, v2, v3, v4;
        if (is64) {
            int4 w0 = *(const int4*)(words + 2 * i0);
            int4 w1 = *(const int4*)(words + 2 * i0 + 4);
            v0 = w0.x; v1 = w0.z; v2 = w1.x; v3 = w1.z;
            v4 = words[2 * (i0 + 4)];
        } else {
            int4 w0 = *(const int4*)(words + i0);
            v0 = w0.x; v1 = w0.y; v2 = w0.z; v3 = w0.w;
            v4 = words[i0 + 4];
        }
        if (i0 == 0)
            for (int g = 0; g <= v0; ++g) g_segoff[g] = 0;
        int va[5] = { v0, v1, v2, v3, v4 };
        #pragma unroll
        for (int j = 0; j < 4; ++j)
            for (int g = va[j] + 1; g <= va[j + 1]; ++g) g_segoff[g] = i0 + j + 1;
    } else {
        for (int i = i0; i < N && i < i0 + 4; ++i) {
            int bi = is64 ? words[2 * i] : words[i];
            if (i == 0)
                for (int g = 0; g <= bi; ++g) g_segoff[g] = 0;
            if (i == N - 1) {
                for (int g = bi + 1; g <= G; ++g) g_segoff[g] = N;
            } else {
                int bn = is64 ? words[2 * (i + 1)] : words[i + 1];
                for (int g = bi + 1; g <= bn; ++g) g_segoff[g] = i + 1;
            }
        }
    }
}

// ---------------------------------------------------------------------------
// Kernel 2 (fused): blocks [0,G): per-segment reduction (streams 256MB);
// blocks [G,G+WTILES): W split+transpose (hidden under the reduce).
// Reduce: 4 warps, warp rg covers rows rg, rg+4, ...; lanes load float4
// streaming (__ldcs); 4x/2x/1x unrolled row batches for MLP.
// feats row: [sum/sqrt(50) | mean | min | max | std] (5 x 128), fp16.
// ---------------------------------------------------------------------------
#define ACC4(v)                                                                \
    do {                                                                       \
        sm0 += (v).x; q0 = fmaf((v).x, (v).x, q0);                             \
        mn0 = fminf(mn0, (v).x); mx0 = fmaxf(mx0, (v).x);                      \
        sm1 += (v).y; q1 = fmaf((v).y, (v).y, q1);                             \
        mn1 = fminf(mn1, (v).y); mx1 = fmaxf(mx1, (v).y);                      \
        sm2 += (v).z; q2 = fmaf((v).z, (v).z, q2);                             \
        mn2 = fminf(mn2, (v).z); mx2 = fmaxf(mx2, (v).z);                      \
        sm3 += (v).w; q3 = fmaf((v).w, (v).w, q3);                             \
        mn3 = fminf(mn3, (v).w); mx3 = fmaxf(mx3, (v).w);                      \
    } while (0)

__global__ __launch_bounds__(128) void seg_reduce_kernel(const float* __restrict__ x,
                                                         const float* __restrict__ W,
                                                         int G)
{
    int t = threadIdx.x;
    int gb = blockIdx.x;

    if (gb >= G) {
        // ---- W split + transpose: 32x32 tile, both sides coalesced ----
        __shared__ float s[32][33];
        int tb = gb - G;
        int k0 = (tb % 20) * 32;
        int n0 = (tb / 20) * 32;
        int tx = t & 31;
        int ty = t >> 5;                   // 0..3
        #pragma unroll
        for (int it = 0; it < 8; ++it) {
            int r = ty + it * 4;           // k offset
            s[r][tx] = W[(size_t)(k0 + r) * 128 + n0 + tx];
        }
        __syncthreads();
        #pragma unroll
        for (int it = 0; it < 8; ++it) {
            int n = ty + it * 4;           // n offset
            float v = s[tx][n];
            __half h = __float2half_rn(v);
            size_t o = (size_t)(n0 + n) * KTOT + k0 + tx;
            g_wh[o] = h;
            g_wl[o] = __float2half_rn(v - __half2float(h));
        }
        return;
    }

    int g = gb;
    int rg   = t >> 5;
    int lane = t & 31;
    int c4   = lane * 4;

    int s0  = g_segoff[g];
    int e0  = g_segoff[g + 1];
    int cnt = e0 - s0;

    float sm0 = 0.f, sm1 = 0.f, sm2 = 0.f, sm3 = 0.f;
    float q0 = 0.f, q1 = 0.f, q2 = 0.f, q3 = 0.f;
    float mn0 = __int_as_float(0x7f800000), mn1 = mn0, mn2 = mn0, mn3 = mn0;
    float mx0 = __int_as_float(0xff800000), mx1 = mx0, mx2 = mx0, mx3 = mx0;

    const float* base = x + (size_t)s0 * D + c4;
    int r = rg;
    for (; r + 12 < cnt; r += 16) {        // 4 float4 in flight
        float4 v0 = __ldcs((const float4*)(base + (size_t)r * D));
        float4 v1 = __ldcs((const float4*)(base + (size_t)(r + 4) * D));
        float4 v2 = __ldcs((const float4*)(base + (size_t)(r + 8) * D));
        float4 v3 = __ldcs((const float4*)(base + (size_t)(r + 12) * D));
        ACC4(v0); ACC4(v1); ACC4(v2); ACC4(v3);
    }
    for (; r + 4 < cnt; r += 8) {          // 2 float4
        float4 v0 = __ldcs((const float4*)(base + (size_t)r * D));
        float4 v1 = __ldcs((const float4*)(base + (size_t)(r + 4) * D));
        ACC4(v0); ACC4(v1);
    }
    for (; r < cnt; r += 4) {
        float4 v0 = __ldcs((const float4*)(base + (size_t)r * D));
        ACC4(v0);
    }

    __shared__ float s_sum[512], s_sq[512], s_mn[512], s_mx[512];
    int sb = rg * 128 + c4;
    s_sum[sb] = sm0; s_sum[sb+1] = sm1; s_sum[sb+2] = sm2; s_sum[sb+3] = sm3;
    s_sq [sb] = q0;  s_sq [sb+1] = q1;  s_sq [sb+2] = q2;  s_sq [sb+3] = q3;
    s_mn [sb] = mn0; s_mn [sb+1] = mn1; s_mn [sb+2] = mn2; s_mn [sb+3] = mn3;
    s_mx [sb] = mx0; s_mx [sb+1] = mx1; s_mx [sb+2] = mx2; s_mx [sb+3] = mx3;
    __syncthreads();

    float sum = s_sum[t] + s_sum[t+128] + s_sum[t+256] + s_sum[t+384];
    float sq  = s_sq [t] + s_sq [t+128] + s_sq [t+256] + s_sq [t+384];
    float mn  = fminf(fminf(s_mn[t], s_mn[t+128]), fminf(s_mn[t+256], s_mn[t+384]));
    float mx  = fmaxf(fmaxf(s_mx[t], s_mx[t+128]), fmaxf(s_mx[t+256], s_mx[t+384]));

    float fc   = fmaxf((float)cnt, 1.0f);
    float mean = sum / fc;
    float stdv = sqrtf(fmaxf(sq / fc - mean * mean, 1e-9f));
    if (cnt == 0) { mn = 0.f; mx = 0.f; }

    size_t fb = (size_t)g * KTOT + t;
    g_fh[fb + 0 * D] = __float2half_rn(sum * 0.14142135623730951f);  // 1/sqrt(50)
    g_fh[fb + 1 * D] = __float2half_rn(mean);
    g_fh[fb + 2 * D] = __float2half_rn(mn);
    g_fh[fb + 3 * D] = __float2half_rn(mx);
    g_fh[fb + 4 * D] = __float2half_rn(stdv);
}

// ---------------------------------------------------------------------------
// Kernel 3: GEMM out[G,128] = feats[G,640] @ W + bias.
// fp16 2-pass (A*Bhi + A*Blo). BM=64, BN=64, BK=64; 256 threads; warp 32x16.
// cp.async double buffer; fragments via ldmatrix.x4.
// ---------------------------------------------------------------------------
#define SSTR    72
#define T_BUF   (64 * SSTR)                 // 4608 halfs
#define STAGE   (3 * T_BUF)                 // 13824 halfs
#define SMEM_ELEMS (2 * STAGE)              // 55296 B

__device__ __forceinline__ void cp16(__half* dst, const __half* src)
{
    unsigned sa = (unsigned)__cvta_generic_to_shared(dst);
    asm volatile("cp.async.cg.shared.global [%0], [%1], 16;\n" :: "r"(sa), "l"(src));
}

#define LDSM4(r0, r1, r2, r3, addr)                                           \
    asm volatile("ldmatrix.sync.aligned.m8n8.x4.shared.b16 {%0,%1,%2,%3}, [%4];" \
        : "=r"(r0), "=r"(r1), "=r"(r2), "=r"(r3) : "r"(addr))

#define MMA_F16(acc, a0, a1, a2, a3, b0, b1)                                  \
    asm volatile(                                                             \
        "mma.sync.aligned.m16n8k16.row.col.f32.f16.f16.f32 "                  \
        "{%0,%1,%2,%3}, {%4,%5,%6,%7}, {%8,%9}, {%0,%1,%2,%3};\n"             \
        : "+f"((acc)[0]), "+f"((acc)[1]), "+f"((acc)[2]), "+f"((acc)[3])      \
        : "r"(a0), "r"(a1), "r"(a2), "r"(a3), "r"(b0), "r"(b1))

__global__ __launch_bounds__(256, 3) void gemm_kernel(const float* __restrict__ bias,
                                                      float* __restrict__ out, int G)
{
    extern __shared__ __half sm[];
    int tid  = threadIdx.x;
    int warp = tid >> 5;
    int lane = tid & 31;
    int wm   = warp >> 2;
    int wn   = warp & 3;
    int bm   = (blockIdx.x >> 1) * 64;
    int bn   = (blockIdx.x & 1) * 64;

    float acc[2][2][4];
    #pragma unroll
    for (int mt = 0; mt < 2; ++mt)
        #pragma unroll
        for (int nt = 0; nt < 2; ++nt)
            #pragma unroll
            for (int r2 = 0; r2 < 4; ++r2) acc[mt][nt][r2] = 0.f;

    unsigned smbase = (unsigned)__cvta_generic_to_shared(sm);
    int mat = lane >> 3, rr = lane & 7;
    unsigned offA0 = ((wm * 32 +      (mat & 1) * 8 + rr) * SSTR + (mat >> 1) * 8) * 2;
    unsigned offA1 = ((wm * 32 + 16 + (mat & 1) * 8 + rr) * SSTR + (mat >> 1) * 8) * 2;
    unsigned offB  = ((unsigned)T_BUF + (wn * 16 + (mat >> 1) * 8 + rr) * SSTR
                      + (mat & 1) * 8) * 2;

    auto load_stage = [&](int s, int kt) {
        int kb = kt * 64;
        #pragma unroll
        for (int i = 0; i < 6; ++i) {
            int c   = tid + i * 256;
            int buf = c >> 9;                  // 0:A 1:Bhi 2:Blo
            int c2  = c & 511;
            int row = c2 >> 3;
            int cw  = c2 & 7;
            const __half* src;
            if (buf == 0)      src = g_fh + (size_t)(bm + row) * KTOT + kb + cw * 8;
            else if (buf == 1) src = g_wh + (size_t)(bn + row) * KTOT + kb + cw * 8;
            else               src = g_wl + (size_t)(bn + row) * KTOT + kb + cw * 8;
            cp16(sm + s * STAGE + buf * T_BUF + row * SSTR + cw * 8, src);
        }
    };

    load_stage(0, 0);
    asm volatile("cp.async.commit_group;\n");

    for (int kt = 0; kt < KTOT / 64; ++kt) {
        int s = kt & 1;
        if (kt + 1 < KTOT / 64) {
            load_stage(s ^ 1, kt + 1);
            asm volatile("cp.async.commit_group;\n");
            asm volatile("cp.async.wait_group 1;\n");
        } else {
            asm volatile("cp.async.wait_group 0;\n");
        }
        __syncthreads();

        unsigned sOff = smbase + (unsigned)(s * STAGE) * 2;

        #pragma unroll
        for (int ks = 0; ks < 4; ++ks) {
            unsigned kOff = (unsigned)(ks * 16) * 2;
            unsigned a0[4], a1[4], bh[4], bl[4];
            LDSM4(a0[0], a0[1], a0[2], a0[3], sOff + offA0 + kOff);
            LDSM4(a1[0], a1[1], a1[2], a1[3], sOff + offA1 + kOff);
            LDSM4(bh[0], bh[1], bh[2], bh[3], sOff + offB + kOff);
            LDSM4(bl[0], bl[1], bl[2], bl[3], sOff + offB + (unsigned)(T_BUF * 2) + kOff);

            MMA_F16(acc[0][0], a0[0], a0[1], a0[2], a0[3], bh[0], bh[1]);
            MMA_F16(acc[0][1], a0[0], a0[1], a0[2], a0[3], bh[2], bh[3]);
            MMA_F16(acc[1][0], a1[0], a1[1], a1[2], a1[3], bh[0], bh[1]);
            MMA_F16(acc[1][1], a1[0], a1[1], a1[2], a1[3], bh[2], bh[3]);
            MMA_F16(acc[0][0], a0[0], a0[1], a0[2], a0[3], bl[0], bl[1]);
            MMA_F16(acc[0][1], a0[0], a0[1], a0[2], a0[3], bl[2], bl[3]);
            MMA_F16(acc[1][0], a1[0], a1[1], a1[2], a1[3], bl[0], bl[1]);
            MMA_F16(acc[1][1], a1[0], a1[1], a1[2], a1[3], bl[2], bl[3]);
        }
        __syncthreads();
    }

    #pragma unroll
    for (int mt = 0; mt < 2; ++mt) {
        #pragma unroll
        for (int nt = 0; nt < 2; ++nt) {
            int row = bm + wm * 32 + mt * 16 + (lane >> 2);
            int n   = bn + wn * 16 + nt * 8 + (lane & 3) * 2;
            float b0 = bias[n];
            float b1 = bias[n + 1];
            if (row < G) {
                float2 v = { acc[mt][nt][0] + b0, acc[mt][nt][1] + b1 };
                *(float2*)(out + (size_t)row * 128 + n) = v;
            }
            if (row + 8 < G) {
                float2 v = { acc[mt][nt][2] + b0, acc[mt][nt][3] + b1 };
                *(float2*)(out + (size_t)(row + 8) * 128 + n) = v;
            }
        }
    }
}

// ---------------------------------------------------------------------------
// Launch. Inputs: x[f32 N*128], batch[int64/int32 N], W[f32 640*128],
// b[f32 128], num_segments (ignored; G = out_size/128).
// ---------------------------------------------------------------------------
extern "C" void kernel_launch(void* const* d_in, const int* in_sizes, int n_in,
                              void* d_out, int out_size)
{
    const float* x     = (const float*)d_in[0];
    const int*   batch = (const int*)d_in[1];
    const float* W     = (const float*)d_in[2];
    const float* bias  = (const float*)d_in[3];
    float*       out   = (float*)d_out;

    int N = in_sizes[0] / D;
    int G = out_size / 128;
    int NB = (N + 1023) / 1024;

    static bool attr_done = false;
    if (!attr_done) {
        cudaFuncSetAttribute(gemm_kernel,
                             cudaFuncAttributeMaxDynamicSharedMemorySize,
                             SMEM_ELEMS * (int)sizeof(__half));
        attr_done = true;
    }

    scan_kernel<<<NB, 256>>>(batch, N, G);
    seg_reduce_kernel<<<G + WTILES, 128>>>(x, W, G);
    gemm_kernel<<<((G + 63) / 64) * 2, 256, SMEM_ELEMS * sizeof(__half)>>>(bias, out, G);
}

// round 8
// speedup vs baseline: 1.5825x; 1.0198x over previous
#include <cuda_runtime.h>
#include <cuda_fp16.h>
#include <cstdint>

#define D       128
#define KTOT    640
#define MAXG    10048        // padded segment capacity (multiple of 64)
#define WTILES  80           // 20 k-tiles x 4 n-tiles of 32x32 for W split

// Scratch (device globals; zero-initialized; feats rows >= G stay 0 forever)
__device__ int g_segoff[MAXG + 1];
__device__ __align__(16) __half g_fh[(size_t)MAXG * KTOT];   // feats fp16
// W TRANSPOSED [n=128][k=640], fp16 hi/lo split
__device__ __align__(16) __half g_wh[128 * KTOT];
__device__ __align__(16) __half g_wl[128 * KTOT];

// ---------------------------------------------------------------------------
// Kernel 1 (scan): boundary scan over sorted batch -> segment offsets.
// 8 ids per thread; int64/int32 detected by a uniform load (words[N-1]==0
// iff int64, since the last id > 0 and high words are 0).
// ---------------------------------------------------------------------------
__global__ __launch_bounds__(256) void scan_kernel(const int* __restrict__ words,
                                                   int N, int G)
{
    const bool is64 = (words[N - 1] == 0);
    int i0 = (blockIdx.x * 256 + threadIdx.x) * 8;
    if (i0 >= N) return;

    if (i0 + 9 <= N) {
        int v[9];
        if (is64) {
            #pragma unroll
            for (int j = 0; j < 4; ++j) {
                int4 w = *(const int4*)(words + 2 * i0 + 4 * j);
                v[2 * j] = w.x; v[2 * j + 1] = w.z;
            }
            v[8] = words[2 * (i0 + 8)];
        } else {
            int4 w0 = *(const int4*)(words + i0);
            int4 w1 = *(const int4*)(words + i0 + 4);
            v[0] = w0.x; v[1] = w0.y; v[2] = w0.z; v[3] = w0.w;
            v[4] = w1.x; v[5] = w1.y; v[6] = w1.z; v[7] = w1.w;
            v[8] = words[i0 + 8];
        }
        if (i0 == 0)
            for (int g = 0; g <= v[0]; ++g) g_segoff[g] = 0;
        #pragma unroll
        for (int j = 0; j < 8; ++j)
            for (int g = v[j] + 1; g <= v[j + 1]; ++g) g_segoff[g] = i0 + j + 1;
    } else {
        for (int i = i0; i < N && i < i0 + 8; ++i) {
            int bi = is64 ? words[2 * i] : words[i];
            if (i == 0)
                for (int g = 0; g <= bi; ++g) g_segoff[g] = 0;
            if (i == N - 1) {
                for (int g = bi + 1; g <= G; ++g) g_segoff[g] = N;
            } else {
                int bn = is64 ? words[2 * (i + 1)] : words[i + 1];
                for (int g = bi + 1; g <= bn; ++g) g_segoff[g] = i + 1;
            }
        }
    }
}

// ---------------------------------------------------------------------------
// Kernel 2 (fused): blocks [0,G): per-segment reduction (streams 256MB);
// blocks [G,G+WTILES): W split+transpose (hidden under the reduce).
// Packed arithmetic: sum/sumsq via f32x2 add/fma (halves fma-pipe work),
// min/max via f16x2 (exact: rn rounding is monotone and feats are fp16).
// feats row: [sum/sqrt(50) | mean | min | max | std] (5 x 128), fp16.
// ---------------------------------------------------------------------------
#define ACCP(v)                                                                \
    do {                                                                       \
        uint64_t p01, p23; unsigned h01u, h23u;                                \
        asm("mov.b64 %0,{%1,%2};" : "=l"(p01) : "f"((v).x), "f"((v).y));       \
        asm("mov.b64 %0,{%1,%2};" : "=l"(p23) : "f"((v).z), "f"((v).w));       \
        asm("add.rn.f32x2 %0,%0,%1;" : "+l"(sum01) : "l"(p01));                \
        asm("add.rn.f32x2 %0,%0,%1;" : "+l"(sum23) : "l"(p23));                \
        asm("fma.rn.f32x2 %0,%1,%1,%0;" : "+l"(sq01) : "l"(p01));              \
        asm("fma.rn.f32x2 %0,%1,%1,%0;" : "+l"(sq23) : "l"(p23));              \
        asm("cvt.rn.f16x2.f32 %0,%1,%2;" : "=r"(h01u) : "f"((v).y), "f"((v).x)); \
        asm("cvt.rn.f16x2.f32 %0,%1,%2;" : "=r"(h23u) : "f"((v).w), "f"((v).z)); \
        __half2 hh01 = *reinterpret_cast<__half2*>(&h01u);                     \
        __half2 hh23 = *reinterpret_cast<__half2*>(&h23u);                     \
        mn01 = __hmin2(mn01, hh01); mx01 = __hmax2(mx01, hh01);                \
        mn23 = __hmin2(mn23, hh23); mx23 = __hmax2(mx23, hh23);                \
    } while (0)

__global__ __launch_bounds__(128) void seg_reduce_kernel(const float* __restrict__ x,
                                                         const float* __restrict__ W,
                                                         int G)
{
    int t = threadIdx.x;
    int gb = blockIdx.x;

    if (gb >= G) {
        // ---- W split + transpose: 32x32 tile, both sides coalesced ----
        __shared__ float s[32][33];
        int tb = gb - G;
        int k0 = (tb % 20) * 32;
        int n0 = (tb / 20) * 32;
        int tx = t & 31;
        int ty = t >> 5;                   // 0..3
        #pragma unroll
        for (int it = 0; it < 8; ++it) {
            int r = ty + it * 4;
            s[r][tx] = W[(size_t)(k0 + r) * 128 + n0 + tx];
        }
        __syncthreads();
        #pragma unroll
        for (int it = 0; it < 8; ++it) {
            int n = ty + it * 4;
            float v = s[tx][n];
            __half h = __float2half_rn(v);
            size_t o = (size_t)(n0 + n) * KTOT + k0 + tx;
            g_wh[o] = h;
            g_wl[o] = __float2half_rn(v - __half2float(h));
        }
        return;
    }

    int g = gb;
    int rg   = t >> 5;
    int lane = t & 31;
    int c4   = lane * 4;

    int s0v = g_segoff[g];
    int e0v = g_segoff[g + 1];
    int cnt = e0v - s0v;

    uint64_t sum01 = 0ULL, sum23 = 0ULL, sq01 = 0ULL, sq23 = 0ULL;
    const __half2 hpos = __halves2half2(__ushort_as_half(0x7C00), __ushort_as_half(0x7C00));
    const __half2 hneg = __halves2half2(__ushort_as_half(0xFC00), __ushort_as_half(0xFC00));
    __half2 mn01 = hpos, mn23 = hpos, mx01 = hneg, mx23 = hneg;

    const float* base = x + (size_t)s0v * D + c4;
    int r = rg;
    for (; r + 12 < cnt; r += 16) {        // 4 float4 in flight
        float4 v0 = __ldcs((const float4*)(base + (size_t)r * D));
        float4 v1 = __ldcs((const float4*)(base + (size_t)(r + 4) * D));
        float4 v2 = __ldcs((const float4*)(base + (size_t)(r + 8) * D));
        float4 v3 = __ldcs((const float4*)(base + (size_t)(r + 12) * D));
        ACCP(v0); ACCP(v1); ACCP(v2); ACCP(v3);
    }
    for (; r + 4 < cnt; r += 8) {
        float4 v0 = __ldcs((const float4*)(base + (size_t)r * D));
        float4 v1 = __ldcs((const float4*)(base + (size_t)(r + 4) * D));
        ACCP(v0); ACCP(v1);
    }
    for (; r < cnt; r += 4) {
        float4 v0 = __ldcs((const float4*)(base + (size_t)r * D));
        ACCP(v0);
    }

    // unpack
    float s0, s1, s2, s3, q0, q1, q2, q3;
    asm("mov.b64 {%0,%1},%2;" : "=f"(s0), "=f"(s1) : "l"(sum01));
    asm("mov.b64 {%0,%1},%2;" : "=f"(s2), "=f"(s3) : "l"(sum23));
    asm("mov.b64 {%0,%1},%2;" : "=f"(q0), "=f"(q1) : "l"(sq01));
    asm("mov.b64 {%0,%1},%2;" : "=f"(q2), "=f"(q3) : "l"(sq23));
    float m0 = __low2float(mn01), m1 = __high2float(mn01);
    float m2 = __low2float(mn23), m3 = __high2float(mn23);
    float M0 = __low2float(mx01), M1 = __high2float(mx01);
    float M2 = __low2float(mx23), M3 = __high2float(mx23);

    __shared__ float s_sum[512], s_sq[512], s_mn[512], s_mx[512];
    int sb = rg * 128 + c4;
    s_sum[sb] = s0; s_sum[sb+1] = s1; s_sum[sb+2] = s2; s_sum[sb+3] = s3;
    s_sq [sb] = q0; s_sq [sb+1] = q1; s_sq [sb+2] = q2; s_sq [sb+3] = q3;
    s_mn [sb] = m0; s_mn [sb+1] = m1; s_mn [sb+2] = m2; s_mn [sb+3] = m3;
    s_mx [sb] = M0; s_mx [sb+1] = M1; s_mx [sb+2] = M2; s_mx [sb+3] = M3;
    __syncthreads();

    float sum = s_sum[t] + s_sum[t+128] + s_sum[t+256] + s_sum[t+384];
    float sq  = s_sq [t] + s_sq [t+128] + s_sq [t+256] + s_sq [t+384];
    float mn  = fminf(fminf(s_mn[t], s_mn[t+128]), fminf(s_mn[t+256], s_mn[t+384]));
    float mx  = fmaxf(fmaxf(s_mx[t], s_mx[t+128]), fmaxf(s_mx[t+256], s_mx[t+384]));

    float fc   = fmaxf((float)cnt, 1.0f);
    float mean = sum / fc;
    float stdv = sqrtf(fmaxf(sq / fc - mean * mean, 1e-9f));
    if (cnt == 0) { mn = 0.f; mx = 0.f; }

    size_t fb = (size_t)g * KTOT + t;
    g_fh[fb + 0 * D] = __float2half_rn(sum * 0.14142135623730951f);  // 1/sqrt(50)
    g_fh[fb + 1 * D] = __float2half_rn(mean);
    g_fh[fb + 2 * D] = __float2half_rn(mn);
    g_fh[fb + 3 * D] = __float2half_rn(mx);
    g_fh[fb + 4 * D] = __float2half_rn(stdv);
}

// ---------------------------------------------------------------------------
// Kernel 3: GEMM out[G,128] = feats[G,640] @ W + bias.
// fp16 2-pass (A*Bhi + A*Blo). BM=64, BN=64, BK=64; 256 threads; warp 32x16.
// cp.async double buffer; fragments via ldmatrix.x4.
// ---------------------------------------------------------------------------
#define SSTR    72
#define T_BUF   (64 * SSTR)                 // 4608 halfs
#define STAGE   (3 * T_BUF)                 // 13824 halfs
#define SMEM_ELEMS (2 * STAGE)              // 55296 B

__device__ __forceinline__ void cp16(__half* dst, const __half* src)
{
    unsigned sa = (unsigned)__cvta_generic_to_shared(dst);
    asm volatile("cp.async.cg.shared.global [%0], [%1], 16;\n" :: "r"(sa), "l"(src));
}

#define LDSM4(r0, r1, r2, r3, addr)                                           \
    asm volatile("ldmatrix.sync.aligned.m8n8.x4.shared.b16 {%0,%1,%2,%3}, [%4];" \
        : "=r"(r0), "=r"(r1), "=r"(r2), "=r"(r3) : "r"(addr))

#define MMA_F16(acc, a0, a1, a2, a3, b0, b1)                                  \
    asm volatile(                                                             \
        "mma.sync.aligned.m16n8k16.row.col.f32.f16.f16.f32 "                  \
        "{%0,%1,%2,%3}, {%4,%5,%6,%7}, {%8,%9}, {%0,%1,%2,%3};\n"             \
        : "+f"((acc)[0]), "+f"((acc)[1]), "+f"((acc)[2]), "+f"((acc)[3])      \
        : "r"(a0), "r"(a1), "r"(a2), "r"(a3), "r"(b0), "r"(b1))

__global__ __launch_bounds__(256, 3) void gemm_kernel(const float* __restrict__ bias,
                                                      float* __restrict__ out, int G)
{
    extern __shared__ __half sm[];
    int tid  = threadIdx.x;
    int warp = tid >> 5;
    int lane = tid & 31;
    int wm   = warp >> 2;
    int wn   = warp & 3;
    int bm   = (blockIdx.x >> 1) * 64;
    int bn   = (blockIdx.x & 1) * 64;

    float acc[2][2][4];
    #pragma unroll
    for (int mt = 0; mt < 2; ++mt)
        #pragma unroll
        for (int nt = 0; nt < 2; ++nt)
            #pragma unroll
            for (int r2 = 0; r2 < 4; ++r2) acc[mt][nt][r2] = 0.f;

    unsigned smbase = (unsigned)__cvta_generic_to_shared(sm);
    int mat = lane >> 3, rr = lane & 7;
    unsigned offA0 = ((wm * 32 +      (mat & 1) * 8 + rr) * SSTR + (mat >> 1) * 8) * 2;
    unsigned offA1 = ((wm * 32 + 16 + (mat & 1) * 8 + rr) * SSTR + (mat >> 1) * 8) * 2;
    unsigned offB  = ((unsigned)T_BUF + (wn * 16 + (mat >> 1) * 8 + rr) * SSTR
                      + (mat & 1) * 8) * 2;

    auto load_stage = [&](int s, int kt) {
        int kb = kt * 64;
        #pragma unroll
        for (int i = 0; i < 6; ++i) {
            int c   = tid + i * 256;
            int buf = c >> 9;                  // 0:A 1:Bhi 2:Blo
            int c2  = c & 511;
            int row = c2 >> 3;
            int cw  = c2 & 7;
            const __half* src;
            if (buf == 0)      src = g_fh + (size_t)(bm + row) * KTOT + kb + cw * 8;
            else if (buf == 1) src = g_wh + (size_t)(bn + row) * KTOT + kb + cw * 8;
            else               src = g_wl + (size_t)(bn + row) * KTOT + kb + cw * 8;
            cp16(sm + s * STAGE + buf * T_BUF + row * SSTR + cw * 8, src);
        }
    };

    load_stage(0, 0);
    asm volatile("cp.async.commit_group;\n");

    for (int kt = 0; kt < KTOT / 64; ++kt) {
        int s = kt & 1;
        if (kt + 1 < KTOT / 64) {
            load_stage(s ^ 1, kt + 1);
            asm volatile("cp.async.commit_group;\n");
            asm volatile("cp.async.wait_group 1;\n");
        } else {
            asm volatile("cp.async.wait_group 0;\n");
        }
        __syncthreads();

        unsigned sOff = smbase + (unsigned)(s * STAGE) * 2;

        #pragma unroll
        for (int ks = 0; ks < 4; ++ks) {
            unsigned kOff = (unsigned)(ks * 16) * 2;
            unsigned a0[4], a1[4], bh[4], bl[4];
            LDSM4(a0[0], a0[1], a0[2], a0[3], sOff + offA0 + kOff);
            LDSM4(a1[0], a1[1], a1[2], a1[3], sOff + offA1 + kOff);
            LDSM4(bh[0], bh[1], bh[2], bh[3], sOff + offB + kOff);
            LDSM4(bl[0], bl[1], bl[2], bl[3], sOff + offB + (unsigned)(T_BUF * 2) + kOff);

            MMA_F16(acc[0][0], a0[0], a0[1], a0[2], a0[3], bh[0], bh[1]);
            MMA_F16(acc[0][1], a0[0], a0[1], a0[2], a0[3], bh[2], bh[3]);
            MMA_F16(acc[1][0], a1[0], a1[1], a1[2], a1[3], bh[0], bh[1]);
            MMA_F16(acc[1][1], a1[0], a1[1], a1[2], a1[3], bh[2], bh[3]);
            MMA_F16(acc[0][0], a0[0], a0[1], a0[2], a0[3], bl[0], bl[1]);
            MMA_F16(acc[0][1], a0[0], a0[1], a0[2], a0[3], bl[2], bl[3]);
            MMA_F16(acc[1][0], a1[0], a1[1], a1[2], a1[3], bl[0], bl[1]);
            MMA_F16(acc[1][1], a1[0], a1[1], a1[2], a1[3], bl[2], bl[3]);
        }
        __syncthreads();
    }

    #pragma unroll
    for (int mt = 0; mt < 2; ++mt) {
        #pragma unroll
        for (int nt = 0; nt < 2; ++nt) {
            int row = bm + wm * 32 + mt * 16 + (lane >> 2);
            int n   = bn + wn * 16 + nt * 8 + (lane & 3) * 2;
            float b0 = bias[n];
            float b1 = bias[n + 1];
            if (row < G) {
                float2 v = { acc[mt][nt][0] + b0, acc[mt][nt][1] + b1 };
                *(float2*)(out + (size_t)row * 128 + n) = v;
            }
            if (row + 8 < G) {
                float2 v = { acc[mt][nt][2] + b0, acc[mt][nt][3] + b1 };
                *(float2*)(out + (size_t)(row + 8) * 128 + n) = v;
            }
        }
    }
}

// ---------------------------------------------------------------------------
// Launch. Inputs: x[f32 N*128], batch[int64/int32 N], W[f32 640*128],
// b[f32 128], num_segments (ignored; G = out_size/128).
// ---------------------------------------------------------------------------
extern "C" void kernel_launch(void* const* d_in, const int* in_sizes, int n_in,
                              void* d_out, int out_size)
{
    const float* x     = (const float*)d_in[0];
    const int*   batch = (const int*)d_in[1];
    const float* W     = (const float*)d_in[2];
    const float* bias  = (const float*)d_in[3];
    float*       out   = (float*)d_out;

    int N = in_sizes[0] / D;
    int G = out_size / 128;
    int NB = (N + 2047) / 2048;

    static bool attr_done = false;
    if (!attr_done) {
        cudaFuncSetAttribute(gemm_kernel,
                             cudaFuncAttributeMaxDynamicSharedMemorySize,
                             SMEM_ELEMS * (int)sizeof(__half));
        attr_done = true;
    }

    scan_kernel<<<NB, 256>>>(batch, N, G);
    seg_reduce_kernel<<<G + WTILES, 128>>>(x, W, G);
    gemm_kernel<<<((G + 63) / 64) * 2, 256, SMEM_ELEMS * sizeof(__half)>>>(bias, out, G);
}